// round 7
// baseline (speedup 1.0000x reference)
#include <cuda_runtime.h>

#define NE   50000
#define NRL  64
#define NT   400000
#define D    128
#define NH   8

// ---------------- scratch (device globals; no allocation) ----------------
__device__ float g_P1[NE * D];      // emb_ent @ Wa[0:128] + ba   (tail part)
__device__ float g_P2[NE * D];      // emb_ent @ Wa[128:256]      (head part)
__device__ float g_G1[NE * D];      // emb_ent @ Wg[0:128] + bg   (msg head part)
__device__ float g_Ra[NRL * D];     // emb_rel @ Wa[256:384]
__device__ float g_Rg[NRL * D];     // emb_rel @ Wg[128:256]
__device__ int   g_off[NE + 1];
__device__ int   g_cur[NE];
__device__ int   g_deg[NE];
__device__ int2  g_ehr[NT];         // CSR payload: (head, rel), grouped by tail

// ---------------- helpers ----------------
__device__ __forceinline__ float tanh_fast(float x) {
    float y;
    asm("tanh.approx.f32 %0, %1;" : "=f"(y) : "f"(x));
    return y;
}
__device__ __forceinline__ unsigned long long dup2(float x) {
    unsigned long long r;
    asm("mov.b64 %0, {%1, %1};" : "=l"(r) : "f"(x));
    return r;
}
__device__ __forceinline__ unsigned long long ffma2(unsigned long long a,
                                                    unsigned long long b,
                                                    unsigned long long c) {
    unsigned long long d;
    asm("fma.rn.f32x2 %0, %1, %2, %3;" : "=l"(d) : "l"(a), "l"(b), "l"(c));
    return d;
}

// ---------------- K0: zero deg + cursors ----------------
__global__ void k_zero() {
    int i = blockIdx.x * blockDim.x + threadIdx.x;
    if (i < NE) { g_deg[i] = 0; g_cur[i] = 0; }
}

// ---------------- K1: degree count ----------------
__global__ void k_count(const int* __restrict__ trip) {
    int i = blockIdx.x * blockDim.x + threadIdx.x;
    if (i < NT) atomicAdd(&g_deg[trip[i * 3 + 2]], 1);
}

// ---------------- K2: Ra, Rg (64 x 128 each) ----------------
__global__ void k_rel(const float* __restrict__ emb_rel,
                      const float* __restrict__ Wa,
                      const float* __restrict__ Wg) {
    __shared__ float x[D];
    int r = blockIdx.x;
    int j = threadIdx.x;
    x[j] = emb_rel[r * D + j];
    __syncthreads();
    float ra = 0.0f, rg = 0.0f;
    #pragma unroll 8
    for (int k = 0; k < D; k++) {
        float xv = x[k];
        ra = fmaf(xv, Wa[(256 + k) * D + j], ra);
        rg = fmaf(xv, Wg[(128 + k) * D + j], rg);
    }
    g_Ra[r * D + j] = ra;
    g_Rg[r * D + j] = rg;
}

// ---------------- K3: per-entity GEMM via packed fma.rn.f32x2 ----------------
// C(50000x128) = X @ W; blockIdx.y picks weight matrix (+ bias fold).
// X stored PRE-DUPLICATED in smem so LDS delivers ready f32x2 operands.
// Double-buffered, one barrier per K-step. 48KB dynamic smem.
__global__ __launch_bounds__(256, 2) void k_ent(const float* __restrict__ X,
                                                const float* __restrict__ Wa,
                                                const float* __restrict__ Wg,
                                                const float* __restrict__ ba,
                                                const float* __restrict__ bg) {
    extern __shared__ float sm[];
    float (*Xs)[16][256] = (float(*)[16][256])sm;            // [buf][k][2*m dup]
    float (*Ws)[16][128] = (float(*)[16][128])(sm + 8192);   // [buf][k][j]

    int tid = threadIdx.x;
    int tx = tid & 15;
    int ty = tid >> 4;
    int m_base = blockIdx.x * 128;
    int w = blockIdx.y;

    const float* Wp = (w == 0) ? Wa : (w == 1) ? (Wa + 128 * D) : Wg;
    float* C = (w == 0) ? g_P1 : (w == 1) ? g_P2 : g_G1;

    int lm  = tid >> 1;
    int lk4 = (tid & 1) * 8;
    int gm_ld = m_base + lm;
    int wr_r  = tid >> 5;
    int wc4   = (tid & 31) * 4;

    unsigned long long acc[2][2][4][2];
    #pragma unroll
    for (int a = 0; a < 2; a++)
        #pragma unroll
        for (int b = 0; b < 2; b++)
            #pragma unroll
            for (int i = 0; i < 4; i++) {
                acc[a][b][i][0] = 0ULL;
                acc[a][b][i][1] = 0ULL;
            }

    float4 xv0, xv1, wv0, wv1;
    {
        xv0 = make_float4(0, 0, 0, 0); xv1 = make_float4(0, 0, 0, 0);
        if (gm_ld < NE) {
            xv0 = *(const float4*)&X[gm_ld * D + lk4];
            xv1 = *(const float4*)&X[gm_ld * D + lk4 + 4];
        }
        wv0 = *(const float4*)&Wp[wr_r * D + wc4];
        wv1 = *(const float4*)&Wp[(wr_r + 8) * D + wc4];
        *(unsigned long long*)&Xs[0][lk4 + 0][2 * lm] = dup2(xv0.x);
        *(unsigned long long*)&Xs[0][lk4 + 1][2 * lm] = dup2(xv0.y);
        *(unsigned long long*)&Xs[0][lk4 + 2][2 * lm] = dup2(xv0.z);
        *(unsigned long long*)&Xs[0][lk4 + 3][2 * lm] = dup2(xv0.w);
        *(unsigned long long*)&Xs[0][lk4 + 4][2 * lm] = dup2(xv1.x);
        *(unsigned long long*)&Xs[0][lk4 + 5][2 * lm] = dup2(xv1.y);
        *(unsigned long long*)&Xs[0][lk4 + 6][2 * lm] = dup2(xv1.z);
        *(unsigned long long*)&Xs[0][lk4 + 7][2 * lm] = dup2(xv1.w);
        *(float4*)&Ws[0][wr_r][wc4]     = wv0;
        *(float4*)&Ws[0][wr_r + 8][wc4] = wv1;
    }
    __syncthreads();

    #pragma unroll
    for (int it = 0; it < 8; ++it) {
        int buf = it & 1;
        if (it < 7) {
            int kb = (it + 1) * 16;
            xv0 = make_float4(0, 0, 0, 0); xv1 = make_float4(0, 0, 0, 0);
            if (gm_ld < NE) {
                xv0 = *(const float4*)&X[gm_ld * D + kb + lk4];
                xv1 = *(const float4*)&X[gm_ld * D + kb + lk4 + 4];
            }
            wv0 = *(const float4*)&Wp[(kb + wr_r) * D + wc4];
            wv1 = *(const float4*)&Wp[(kb + wr_r + 8) * D + wc4];
        }
        #pragma unroll
        for (int kk = 0; kk < 16; ++kk) {
            const ulonglong2* xr = (const ulonglong2*)&Xs[buf][kk][0];
            ulonglong2 xa0 = xr[2 * ty];
            ulonglong2 xa1 = xr[2 * ty + 1];
            ulonglong2 xb0 = xr[32 + 2 * ty];
            ulonglong2 xb1 = xr[32 + 2 * ty + 1];
            ulonglong2 wA = *(const ulonglong2*)&Ws[buf][kk][tx * 4];
            ulonglong2 wB = *(const ulonglong2*)&Ws[buf][kk][64 + tx * 4];

            unsigned long long xd[2][4] = {
                { xa0.x, xa0.y, xa1.x, xa1.y },
                { xb0.x, xb0.y, xb1.x, xb1.y }
            };
            #pragma unroll
            for (int a = 0; a < 2; a++)
                #pragma unroll
                for (int i = 0; i < 4; i++) {
                    acc[a][0][i][0] = ffma2(xd[a][i], wA.x, acc[a][0][i][0]);
                    acc[a][0][i][1] = ffma2(xd[a][i], wA.y, acc[a][0][i][1]);
                    acc[a][1][i][0] = ffma2(xd[a][i], wB.x, acc[a][1][i][0]);
                    acc[a][1][i][1] = ffma2(xd[a][i], wB.y, acc[a][1][i][1]);
                }
        }
        if (it < 7) {
            int nb = buf ^ 1;
            *(unsigned long long*)&Xs[nb][lk4 + 0][2 * lm] = dup2(xv0.x);
            *(unsigned long long*)&Xs[nb][lk4 + 1][2 * lm] = dup2(xv0.y);
            *(unsigned long long*)&Xs[nb][lk4 + 2][2 * lm] = dup2(xv0.z);
            *(unsigned long long*)&Xs[nb][lk4 + 3][2 * lm] = dup2(xv0.w);
            *(unsigned long long*)&Xs[nb][lk4 + 4][2 * lm] = dup2(xv1.x);
            *(unsigned long long*)&Xs[nb][lk4 + 5][2 * lm] = dup2(xv1.y);
            *(unsigned long long*)&Xs[nb][lk4 + 6][2 * lm] = dup2(xv1.z);
            *(unsigned long long*)&Xs[nb][lk4 + 7][2 * lm] = dup2(xv1.w);
            *(float4*)&Ws[nb][wr_r][wc4]     = wv0;
            *(float4*)&Ws[nb][wr_r + 8][wc4] = wv1;
        }
        __syncthreads();
    }

    #pragma unroll
    for (int a = 0; a < 2; a++)
        #pragma unroll
        for (int i = 0; i < 4; i++) {
            int gm = m_base + a * 64 + ty * 4 + i;
            if (gm < NE) {
                #pragma unroll
                for (int b = 0; b < 2; b++) {
                    int col = b * 64 + tx * 4;
                    float4 bias = make_float4(0, 0, 0, 0);
                    if (w == 0) bias = *(const float4*)&ba[col];
                    else if (w == 2) bias = *(const float4*)&bg[col];
                    uint2 lo = *reinterpret_cast<uint2*>(&acc[a][b][i][0]);
                    uint2 hi = *reinterpret_cast<uint2*>(&acc[a][b][i][1]);
                    float4 v = make_float4(__uint_as_float(lo.x) + bias.x,
                                           __uint_as_float(lo.y) + bias.y,
                                           __uint_as_float(hi.x) + bias.z,
                                           __uint_as_float(hi.y) + bias.w);
                    *(float4*)&C[gm * D + col] = v;
                }
            }
        }
}

// ---------------- K4: exclusive prefix scan of degrees (single block) ------
__global__ void k_scan() {
    __shared__ int s[1024];
    int t = threadIdx.x;
    const int CH = (NE + 1023) / 1024;  // 49
    int base = t * CH;
    int sum = 0;
    #pragma unroll
    for (int i = 0; i < CH; i++)
        if (base + i < NE) sum += g_deg[base + i];
    s[t] = sum;
    __syncthreads();
    for (int o = 1; o < 1024; o <<= 1) {
        int v = (t >= o) ? s[t - o] : 0;
        __syncthreads();
        s[t] += v;
        __syncthreads();
    }
    int run = (t > 0) ? s[t - 1] : 0;
    #pragma unroll
    for (int i = 0; i < CH; i++) {
        if (base + i < NE) {
            g_off[base + i] = run;
            run += g_deg[base + i];
        }
    }
    if (t == 1023) g_off[NE] = s[1023];
}

// ---------------- K5: scatter (head, rel) into CSR ----------------
__global__ void k_scatter(const int* __restrict__ trip) {
    int i = blockIdx.x * blockDim.x + threadIdx.x;
    if (i < NT) {
        int hd = trip[i * 3 + 0];
        int rl = trip[i * 3 + 1];
        int tl = trip[i * 3 + 2];
        int p = atomicAdd(&g_cur[tl], 1);
        g_ehr[g_off[tl] + p] = make_int2(hd, rl);
    }
}

// ---------------- K6: fused attention + softmax + aggregation -------------
// 1 warp per entity. Edge IDs staged cooperatively (1 coalesced int2 load per
// 32 edges, broadcast via shfl) so gather addresses have no serial memory dep;
// inner loop unrolled x2 with mask-predicated second edge -> 8 concurrent
// 512B gathers in flight. ba folded into P1, bg into G1. No max-subtraction:
// |attn_raw| <= sum|av| ~ 1.5, exp safe, softmax shift-invariant.
__global__ __launch_bounds__(256) void k_gather(const float* __restrict__ av,
                                                float* __restrict__ out) {
    int e = (blockIdx.x * blockDim.x + threadIdx.x) >> 5;
    int lane = threadIdx.x & 31;
    if (e >= NE) return;
    int o0 = g_off[e];
    int deg = g_off[e + 1] - o0;

    int j = lane * 4;
    float4 p1  = *(const float4*)&g_P1[e * D + j];   // includes ba
    float4 av4 = *(const float4*)&av[j];
    // self-edge entity rows: issue early, consumed after the loop
    float4 p2s = *(const float4*)&g_P2[e * D + j];
    float4 g1s = *(const float4*)&g_G1[e * D + j];

    float ax = 0.f, ay = 0.f, az = 0.f, aw = 0.f;
    float denom = 0.f;
    float sax = 0.f, say = 0.f, saz = 0.f, saw = 0.f;  // sum Ra[rel]
    float sgx = 0.f, sgy = 0.f, sgz = 0.f, sgw = 0.f;  // sum Rg[rel]

    for (int base = 0; base < deg; base += 32) {
        int n = min(32, deg - base);
        int2 eh = make_int2(0, 0);
        if (lane < n) eh = g_ehr[o0 + base + lane];   // one coalesced load

        for (int jj = 0; jj < n; jj += 2) {
            int h0 = __shfl_sync(0xffffffffu, eh.x, jj);
            int r0 = __shfl_sync(0xffffffffu, eh.y, jj);
            int j1 = min(jj + 1, n - 1);
            int h1 = __shfl_sync(0xffffffffu, eh.x, j1);
            int r1 = __shfl_sync(0xffffffffu, eh.y, j1);
            float m1 = (jj + 1 < n) ? 1.0f : 0.0f;

            float4 p2a = *(const float4*)&g_P2[h0 * D + j];
            float4 g1a = *(const float4*)&g_G1[h0 * D + j];
            float4 p2b = *(const float4*)&g_P2[h1 * D + j];
            float4 g1b = *(const float4*)&g_G1[h1 * D + j];
            float4 raa = *(const float4*)&g_Ra[r0 * D + j];
            float4 rga = *(const float4*)&g_Rg[r0 * D + j];
            float4 rab = *(const float4*)&g_Ra[r1 * D + j];
            float4 rgb = *(const float4*)&g_Rg[r1 * D + j];

            // edge A
            float s0 = 0.f;
            s0 = fmaf(tanh_fast(p1.x + p2a.x + raa.x), av4.x, s0);
            s0 = fmaf(tanh_fast(p1.y + p2a.y + raa.y), av4.y, s0);
            s0 = fmaf(tanh_fast(p1.z + p2a.z + raa.z), av4.z, s0);
            s0 = fmaf(tanh_fast(p1.w + p2a.w + raa.w), av4.w, s0);
            // edge B
            float s1 = 0.f;
            s1 = fmaf(tanh_fast(p1.x + p2b.x + rab.x), av4.x, s1);
            s1 = fmaf(tanh_fast(p1.y + p2b.y + rab.y), av4.y, s1);
            s1 = fmaf(tanh_fast(p1.z + p2b.z + rab.z), av4.z, s1);
            s1 = fmaf(tanh_fast(p1.w + p2b.w + rab.w), av4.w, s1);

            s0 += __shfl_xor_sync(0xffffffffu, s0, 1);
            s0 += __shfl_xor_sync(0xffffffffu, s0, 2);
            s1 += __shfl_xor_sync(0xffffffffu, s1, 1);
            s1 += __shfl_xor_sync(0xffffffffu, s1, 2);

            float ev0 = __expf(s0);
            float ev1 = m1 * __expf(s1);

            ax = fmaf(ev0, g1a.x + rga.x, ax);
            ay = fmaf(ev0, g1a.y + rga.y, ay);
            az = fmaf(ev0, g1a.z + rga.z, az);
            aw = fmaf(ev0, g1a.w + rga.w, aw);
            ax = fmaf(ev1, g1b.x + rgb.x, ax);
            ay = fmaf(ev1, g1b.y + rgb.y, ay);
            az = fmaf(ev1, g1b.z + rgb.z, az);
            aw = fmaf(ev1, g1b.w + rgb.w, aw);
            denom += ev0 + ev1;

            sax += raa.x + m1 * rab.x; say += raa.y + m1 * rab.y;
            saz += raa.z + m1 * rab.z; saw += raa.w + m1 * rab.w;
            sgx += rga.x + m1 * rgb.x; sgy += rga.y + m1 * rgb.y;
            sgz += rga.z + m1 * rgb.z; sgw += rga.w + m1 * rgb.w;
        }
    }

    // ---- self edge: head = e, rel-feat = mean of Ra/Rg over incoming edges
    {
        float inv = (deg > 0) ? (1.0f / (float)deg) : 0.0f;
        float s = 0.f;
        s = fmaf(tanh_fast(p1.x + p2s.x + sax * inv), av4.x, s);
        s = fmaf(tanh_fast(p1.y + p2s.y + say * inv), av4.y, s);
        s = fmaf(tanh_fast(p1.z + p2s.z + saz * inv), av4.z, s);
        s = fmaf(tanh_fast(p1.w + p2s.w + saw * inv), av4.w, s);
        s += __shfl_xor_sync(0xffffffffu, s, 1);
        s += __shfl_xor_sync(0xffffffffu, s, 2);
        float ev = __expf(s);
        ax = fmaf(ev, g1s.x + sgx * inv, ax);
        ay = fmaf(ev, g1s.y + sgy * inv, ay);
        az = fmaf(ev, g1s.z + sgz * inv, az);
        aw = fmaf(ev, g1s.w + sgw * inv, aw);
        denom += ev;
    }

    float inv = 1.0f / denom;
    *(float4*)&out[e * D + j] = make_float4(ax * inv, ay * inv, az * inv, aw * inv);
}

// ---------------- launch: fork CSR build + rel GEMV onto side stream -------
extern "C" void kernel_launch(void* const* d_in, const int* in_sizes, int n_in,
                              void* d_out, int out_size) {
    const float* emb_ent = (const float*)d_in[0];
    const float* emb_rel = (const float*)d_in[1];
    const int*   trip    = (const int*)d_in[2];
    const float* Wa      = (const float*)d_in[3];
    const float* ba      = (const float*)d_in[4];
    const float* av      = (const float*)d_in[5];
    const float* Wg      = (const float*)d_in[6];
    const float* bg      = (const float*)d_in[7];
    float* out = (float*)d_out;

    static cudaStream_t s2 = nullptr;
    static cudaEvent_t evF = nullptr, evJ = nullptr;
    if (s2 == nullptr) {
        cudaStreamCreateWithFlags(&s2, cudaStreamNonBlocking);
        cudaEventCreateWithFlags(&evF, cudaEventDisableTiming);
        cudaEventCreateWithFlags(&evJ, cudaEventDisableTiming);
        cudaFuncSetAttribute(k_ent, cudaFuncAttributeMaxDynamicSharedMemorySize, 49152);
    }

    // fork: CSR build + rel GEMV on side stream (only k_gather consumes them)
    cudaEventRecord(evF, 0);
    cudaStreamWaitEvent(s2, evF, 0);
    k_rel<<<NRL, 128, 0, s2>>>(emb_rel, Wa, Wg);
    k_zero<<<(NE + 255) / 256, 256, 0, s2>>>();
    k_count<<<(NT + 255) / 256, 256, 0, s2>>>(trip);
    k_scan<<<1, 1024, 0, s2>>>();
    k_scatter<<<(NT + 255) / 256, 256, 0, s2>>>(trip);
    cudaEventRecord(evJ, s2);

    // main stream: entity GEMM
    dim3 ent_grid((NE + 127) / 128, 3);
    k_ent<<<ent_grid, 256, 49152>>>(emb_ent, Wa, Wg, ba, bg);

    // join, then fused gather
    cudaStreamWaitEvent(0, evJ, 0);
    k_gather<<<(NE * 32 + 255) / 256, 256>>>(av, out);
}

// round 9
// speedup vs baseline: 1.3182x; 1.3182x over previous
#include <cuda_runtime.h>

#define NE   50000
#define NRL  64
#define NT   400000
#define D    128
#define NH   8
#define NBLK 196   // ceil(NE/256)

// ---------------- scratch (device globals; no allocation) ----------------
__device__ float g_P1[NE * D];      // emb_ent @ Wa[0:128] + ba   (tail part)
__device__ float g_P2[NE * D];      // emb_ent @ Wa[128:256]      (head part)
__device__ float g_G1[NE * D];      // emb_ent @ Wg[0:128] + bg   (msg head part)
__device__ float g_Ra[NRL * D];     // emb_rel @ Wa[256:384]
__device__ float g_Rg[NRL * D];     // emb_rel @ Wg[128:256]
__device__ int   g_off[NE + 1];
__device__ int   g_cur[NE];
__device__ int   g_deg[NE];
__device__ int   g_part[256];
__device__ int2  g_ehr[NT];         // CSR payload: (head, rel), grouped by tail

// ---------------- helpers ----------------
__device__ __forceinline__ float tanh_fast(float x) {
    float y;
    asm("tanh.approx.f32 %0, %1;" : "=f"(y) : "f"(x));
    return y;
}
__device__ __forceinline__ unsigned long long dup2(float x) {
    unsigned long long r;
    asm("mov.b64 %0, {%1, %1};" : "=l"(r) : "f"(x));
    return r;
}
__device__ __forceinline__ unsigned long long ffma2(unsigned long long a,
                                                    unsigned long long b,
                                                    unsigned long long c) {
    unsigned long long d;
    asm("fma.rn.f32x2 %0, %1, %2, %3;" : "=l"(d) : "l"(a), "l"(b), "l"(c));
    return d;
}

// ---------------- K0: zero deg + cursors ----------------
__global__ void k_zero() {
    int i = blockIdx.x * blockDim.x + threadIdx.x;
    if (i < NE) { g_deg[i] = 0; g_cur[i] = 0; }
}

// ---------------- K1: degree count ----------------
__global__ void k_count(const int* __restrict__ trip) {
    int i = blockIdx.x * blockDim.x + threadIdx.x;
    if (i < NT) atomicAdd(&g_deg[trip[i * 3 + 2]], 1);
}

// ---------------- K2: Ra, Rg (64 x 128 each) ----------------
__global__ void k_rel(const float* __restrict__ emb_rel,
                      const float* __restrict__ Wa,
                      const float* __restrict__ Wg) {
    __shared__ float x[D];
    int r = blockIdx.x;
    int j = threadIdx.x;
    x[j] = emb_rel[r * D + j];
    __syncthreads();
    float ra = 0.0f, rg = 0.0f;
    #pragma unroll 8
    for (int k = 0; k < D; k++) {
        float xv = x[k];
        ra = fmaf(xv, Wa[(256 + k) * D + j], ra);
        rg = fmaf(xv, Wg[(128 + k) * D + j], rg);
    }
    g_Ra[r * D + j] = ra;
    g_Rg[r * D + j] = rg;
}

// ---------------- K3: per-entity GEMM via packed fma.rn.f32x2 ----------------
__global__ __launch_bounds__(256, 2) void k_ent(const float* __restrict__ X,
                                                const float* __restrict__ Wa,
                                                const float* __restrict__ Wg,
                                                const float* __restrict__ ba,
                                                const float* __restrict__ bg) {
    extern __shared__ float sm[];
    float (*Xs)[16][256] = (float(*)[16][256])sm;            // [buf][k][2*m dup]
    float (*Ws)[16][128] = (float(*)[16][128])(sm + 8192);   // [buf][k][j]

    int tid = threadIdx.x;
    int tx = tid & 15;
    int ty = tid >> 4;
    int m_base = blockIdx.x * 128;
    int w = blockIdx.y;

    const float* Wp = (w == 0) ? Wa : (w == 1) ? (Wa + 128 * D) : Wg;
    float* C = (w == 0) ? g_P1 : (w == 1) ? g_P2 : g_G1;

    int lm  = tid >> 1;
    int lk4 = (tid & 1) * 8;
    int gm_ld = m_base + lm;
    int wr_r  = tid >> 5;
    int wc4   = (tid & 31) * 4;

    unsigned long long acc[2][2][4][2];
    #pragma unroll
    for (int a = 0; a < 2; a++)
        #pragma unroll
        for (int b = 0; b < 2; b++)
            #pragma unroll
            for (int i = 0; i < 4; i++) {
                acc[a][b][i][0] = 0ULL;
                acc[a][b][i][1] = 0ULL;
            }

    float4 xv0, xv1, wv0, wv1;
    {
        xv0 = make_float4(0, 0, 0, 0); xv1 = make_float4(0, 0, 0, 0);
        if (gm_ld < NE) {
            xv0 = *(const float4*)&X[gm_ld * D + lk4];
            xv1 = *(const float4*)&X[gm_ld * D + lk4 + 4];
        }
        wv0 = *(const float4*)&Wp[wr_r * D + wc4];
        wv1 = *(const float4*)&Wp[(wr_r + 8) * D + wc4];
        *(unsigned long long*)&Xs[0][lk4 + 0][2 * lm] = dup2(xv0.x);
        *(unsigned long long*)&Xs[0][lk4 + 1][2 * lm] = dup2(xv0.y);
        *(unsigned long long*)&Xs[0][lk4 + 2][2 * lm] = dup2(xv0.z);
        *(unsigned long long*)&Xs[0][lk4 + 3][2 * lm] = dup2(xv0.w);
        *(unsigned long long*)&Xs[0][lk4 + 4][2 * lm] = dup2(xv1.x);
        *(unsigned long long*)&Xs[0][lk4 + 5][2 * lm] = dup2(xv1.y);
        *(unsigned long long*)&Xs[0][lk4 + 6][2 * lm] = dup2(xv1.z);
        *(unsigned long long*)&Xs[0][lk4 + 7][2 * lm] = dup2(xv1.w);
        *(float4*)&Ws[0][wr_r][wc4]     = wv0;
        *(float4*)&Ws[0][wr_r + 8][wc4] = wv1;
    }
    __syncthreads();

    #pragma unroll
    for (int it = 0; it < 8; ++it) {
        int buf = it & 1;
        if (it < 7) {
            int kb = (it + 1) * 16;
            xv0 = make_float4(0, 0, 0, 0); xv1 = make_float4(0, 0, 0, 0);
            if (gm_ld < NE) {
                xv0 = *(const float4*)&X[gm_ld * D + kb + lk4];
                xv1 = *(const float4*)&X[gm_ld * D + kb + lk4 + 4];
            }
            wv0 = *(const float4*)&Wp[(kb + wr_r) * D + wc4];
            wv1 = *(const float4*)&Wp[(kb + wr_r + 8) * D + wc4];
        }
        #pragma unroll
        for (int kk = 0; kk < 16; ++kk) {
            const ulonglong2* xr = (const ulonglong2*)&Xs[buf][kk][0];
            ulonglong2 xa0 = xr[2 * ty];
            ulonglong2 xa1 = xr[2 * ty + 1];
            ulonglong2 xb0 = xr[32 + 2 * ty];
            ulonglong2 xb1 = xr[32 + 2 * ty + 1];
            ulonglong2 wA = *(const ulonglong2*)&Ws[buf][kk][tx * 4];
            ulonglong2 wB = *(const ulonglong2*)&Ws[buf][kk][64 + tx * 4];

            unsigned long long xd[2][4] = {
                { xa0.x, xa0.y, xa1.x, xa1.y },
                { xb0.x, xb0.y, xb1.x, xb1.y }
            };
            #pragma unroll
            for (int a = 0; a < 2; a++)
                #pragma unroll
                for (int i = 0; i < 4; i++) {
                    acc[a][0][i][0] = ffma2(xd[a][i], wA.x, acc[a][0][i][0]);
                    acc[a][0][i][1] = ffma2(xd[a][i], wA.y, acc[a][0][i][1]);
                    acc[a][1][i][0] = ffma2(xd[a][i], wB.x, acc[a][1][i][0]);
                    acc[a][1][i][1] = ffma2(xd[a][i], wB.y, acc[a][1][i][1]);
                }
        }
        if (it < 7) {
            int nb = buf ^ 1;
            *(unsigned long long*)&Xs[nb][lk4 + 0][2 * lm] = dup2(xv0.x);
            *(unsigned long long*)&Xs[nb][lk4 + 1][2 * lm] = dup2(xv0.y);
            *(unsigned long long*)&Xs[nb][lk4 + 2][2 * lm] = dup2(xv0.z);
            *(unsigned long long*)&Xs[nb][lk4 + 3][2 * lm] = dup2(xv0.w);
            *(unsigned long long*)&Xs[nb][lk4 + 4][2 * lm] = dup2(xv1.x);
            *(unsigned long long*)&Xs[nb][lk4 + 5][2 * lm] = dup2(xv1.y);
            *(unsigned long long*)&Xs[nb][lk4 + 6][2 * lm] = dup2(xv1.z);
            *(unsigned long long*)&Xs[nb][lk4 + 7][2 * lm] = dup2(xv1.w);
            *(float4*)&Ws[nb][wr_r][wc4]     = wv0;
            *(float4*)&Ws[nb][wr_r + 8][wc4] = wv1;
        }
        __syncthreads();
    }

    #pragma unroll
    for (int a = 0; a < 2; a++)
        #pragma unroll
        for (int i = 0; i < 4; i++) {
            int gm = m_base + a * 64 + ty * 4 + i;
            if (gm < NE) {
                #pragma unroll
                for (int b = 0; b < 2; b++) {
                    int col = b * 64 + tx * 4;
                    float4 bias = make_float4(0, 0, 0, 0);
                    if (w == 0) bias = *(const float4*)&ba[col];
                    else if (w == 2) bias = *(const float4*)&bg[col];
                    uint2 lo = *reinterpret_cast<uint2*>(&acc[a][b][i][0]);
                    uint2 hi = *reinterpret_cast<uint2*>(&acc[a][b][i][1]);
                    float4 v = make_float4(__uint_as_float(lo.x) + bias.x,
                                           __uint_as_float(lo.y) + bias.y,
                                           __uint_as_float(hi.x) + bias.z,
                                           __uint_as_float(hi.y) + bias.w);
                    *(float4*)&C[gm * D + col] = v;
                }
            }
        }
}

// ---------------- K4a/b/c: decoupled 3-phase exclusive scan of degrees -----
__global__ void k_scanA() {
    __shared__ int s[256];
    int t = threadIdx.x;
    int i = blockIdx.x * 256 + t;
    s[t] = (i < NE) ? g_deg[i] : 0;
    __syncthreads();
    #pragma unroll
    for (int o = 128; o > 0; o >>= 1) {
        if (t < o) s[t] += s[t + o];
        __syncthreads();
    }
    if (t == 0) g_part[blockIdx.x] = s[0];
}
__global__ void k_scanB() {   // 1 block, 256 threads; scans NBLK partials
    __shared__ int s[256];
    int t = threadIdx.x;
    int v = (t < NBLK) ? g_part[t] : 0;
    s[t] = v;
    __syncthreads();
    #pragma unroll
    for (int o = 1; o < 256; o <<= 1) {
        int u = (t >= o) ? s[t - o] : 0;
        __syncthreads();
        s[t] += u;
        __syncthreads();
    }
    if (t < NBLK) g_part[t] = s[t] - v;          // exclusive
    if (t == NBLK - 1) g_off[NE] = s[t];         // total edge count
}
__global__ void k_scanC() {
    __shared__ int s[256];
    int t = threadIdx.x;
    int i = blockIdx.x * 256 + t;
    int v = (i < NE) ? g_deg[i] : 0;
    s[t] = v;
    __syncthreads();
    #pragma unroll
    for (int o = 1; o < 256; o <<= 1) {
        int u = (t >= o) ? s[t - o] : 0;
        __syncthreads();
        s[t] += u;
        __syncthreads();
    }
    if (i < NE) g_off[i] = g_part[blockIdx.x] + s[t] - v;
}

// ---------------- K5: scatter (head, rel) into CSR ----------------
__global__ void k_scatter(const int* __restrict__ trip) {
    int i = blockIdx.x * blockDim.x + threadIdx.x;
    if (i < NT) {
        int hd = trip[i * 3 + 0];
        int rl = trip[i * 3 + 1];
        int tl = trip[i * 3 + 2];
        int p = atomicAdd(&g_cur[tl], 1);
        g_ehr[g_off[tl] + p] = make_int2(hd, rl);
    }
}

// ---------------- K6: fused attention + softmax + aggregation -------------
// 1 warp per entity, software-pipelined edge loop (R5 proven version).
// ba folded into P1, bg folded into G1 (exact). No max-subtraction:
// |attn_raw| <= sum|av| ~ 1.5, exp safe, softmax shift-invariant.
__global__ __launch_bounds__(256) void k_gather(const float* __restrict__ av,
                                                float* __restrict__ out) {
    int e = (blockIdx.x * blockDim.x + threadIdx.x) >> 5;
    int lane = threadIdx.x & 31;
    if (e >= NE) return;
    int o0 = g_off[e];
    int deg = g_off[e + 1] - o0;

    int j = lane * 4;
    float4 p1  = *(const float4*)&g_P1[e * D + j];   // includes ba
    float4 av4 = *(const float4*)&av[j];

    float ax = 0.f, ay = 0.f, az = 0.f, aw = 0.f;
    float denom = 0.f;
    float sax = 0.f, say = 0.f, saz = 0.f, saw = 0.f;  // sum Ra[rel]
    float sgx = 0.f, sgy = 0.f, sgz = 0.f, sgw = 0.f;  // sum Rg[rel]

    float4 p2c, rac, g1c, rgc;
    if (deg > 0) {
        int2 hr = g_ehr[o0];
        p2c = *(const float4*)&g_P2[hr.x * D + j];
        rac = *(const float4*)&g_Ra[hr.y * D + j];
        g1c = *(const float4*)&g_G1[hr.x * D + j];
        rgc = *(const float4*)&g_Rg[hr.y * D + j];
    }
    for (int jj = 0; jj < deg; ++jj) {
        float4 p2n, ran, g1n, rgn;
        if (jj + 1 < deg) {
            int2 hr = g_ehr[o0 + jj + 1];
            p2n = *(const float4*)&g_P2[hr.x * D + j];
            ran = *(const float4*)&g_Ra[hr.y * D + j];
            g1n = *(const float4*)&g_G1[hr.x * D + j];
            rgn = *(const float4*)&g_Rg[hr.y * D + j];
        }
        float s = 0.f;
        s = fmaf(tanh_fast(p1.x + p2c.x + rac.x), av4.x, s);
        s = fmaf(tanh_fast(p1.y + p2c.y + rac.y), av4.y, s);
        s = fmaf(tanh_fast(p1.z + p2c.z + rac.z), av4.z, s);
        s = fmaf(tanh_fast(p1.w + p2c.w + rac.w), av4.w, s);
        s += __shfl_xor_sync(0xffffffffu, s, 1);
        s += __shfl_xor_sync(0xffffffffu, s, 2);
        float ev = __expf(s);

        ax = fmaf(ev, g1c.x + rgc.x, ax);   // g1 includes bg
        ay = fmaf(ev, g1c.y + rgc.y, ay);
        az = fmaf(ev, g1c.z + rgc.z, az);
        aw = fmaf(ev, g1c.w + rgc.w, aw);
        denom += ev;

        sax += rac.x; say += rac.y; saz += rac.z; saw += rac.w;
        sgx += rgc.x; sgy += rgc.y; sgz += rgc.z; sgw += rgc.w;

        p2c = p2n; rac = ran; g1c = g1n; rgc = rgn;
    }

    // ---- self edge: head = e, rel-feat = mean of Ra/Rg over incoming edges
    {
        float inv = (deg > 0) ? (1.0f / (float)deg) : 0.0f;
        float4 p2 = *(const float4*)&g_P2[e * D + j];
        float4 g1 = *(const float4*)&g_G1[e * D + j];
        float s = 0.f;
        s = fmaf(tanh_fast(p1.x + p2.x + sax * inv), av4.x, s);
        s = fmaf(tanh_fast(p1.y + p2.y + say * inv), av4.y, s);
        s = fmaf(tanh_fast(p1.z + p2.z + saz * inv), av4.z, s);
        s = fmaf(tanh_fast(p1.w + p2.w + saw * inv), av4.w, s);
        s += __shfl_xor_sync(0xffffffffu, s, 1);
        s += __shfl_xor_sync(0xffffffffu, s, 2);
        float ev = __expf(s);
        ax = fmaf(ev, g1.x + sgx * inv, ax);
        ay = fmaf(ev, g1.y + sgy * inv, ay);
        az = fmaf(ev, g1.z + sgz * inv, az);
        aw = fmaf(ev, g1.w + sgw * inv, aw);
        denom += ev;
    }

    float inv = 1.0f / denom;
    *(float4*)&out[e * D + j] = make_float4(ax * inv, ay * inv, az * inv, aw * inv);
}

// ---------------- launch: fork CSR build onto side stream ----------------
extern "C" void kernel_launch(void* const* d_in, const int* in_sizes, int n_in,
                              void* d_out, int out_size) {
    const float* emb_ent = (const float*)d_in[0];
    const float* emb_rel = (const float*)d_in[1];
    const int*   trip    = (const int*)d_in[2];
    const float* Wa      = (const float*)d_in[3];
    const float* ba      = (const float*)d_in[4];
    const float* av      = (const float*)d_in[5];
    const float* Wg      = (const float*)d_in[6];
    const float* bg      = (const float*)d_in[7];
    float* out = (float*)d_out;

    static cudaStream_t s2 = nullptr;
    static cudaEvent_t evF = nullptr, evJ = nullptr;
    if (s2 == nullptr) {
        cudaStreamCreateWithFlags(&s2, cudaStreamNonBlocking);
        cudaEventCreateWithFlags(&evF, cudaEventDisableTiming);
        cudaEventCreateWithFlags(&evJ, cudaEventDisableTiming);
        cudaFuncSetAttribute(k_ent, cudaFuncAttributeMaxDynamicSharedMemorySize, 49152);
    }

    // fork: CSR build chain on side stream (decoupled parallel scan)
    cudaEventRecord(evF, 0);
    cudaStreamWaitEvent(s2, evF, 0);
    k_zero<<<(NE + 255) / 256, 256, 0, s2>>>();
    k_count<<<(NT + 255) / 256, 256, 0, s2>>>(trip);
    k_scanA<<<NBLK, 256, 0, s2>>>();
    k_scanB<<<1, 256, 0, s2>>>();
    k_scanC<<<NBLK, 256, 0, s2>>>();
    k_scatter<<<(NT + 255) / 256, 256, 0, s2>>>(trip);
    cudaEventRecord(evJ, s2);

    // main stream: GEMM chain
    k_rel<<<NRL, 128>>>(emb_rel, Wa, Wg);
    dim3 ent_grid((NE + 127) / 128, 3);
    k_ent<<<ent_grid, 256, 49152>>>(emb_ent, Wa, Wg, ba, bg);

    // join, then fused gather
    cudaStreamWaitEvent(0, evJ, 0);
    k_gather<<<(NE * 32 + 255) / 256, 256>>>(av, out);
}